// round 6
// baseline (speedup 1.0000x reference)
#include <cuda_runtime.h>
#include <cuda_fp16.h>
#include <cstdint>
#include <math.h>

// ============================================================================
// DUQ head via mma.sync (HMMA) 3xFP16-split GEMM, shared-operand form.
// out[b,c,p] = exp(-3.125 * sum_e (emb[p, c*16+e] - cent[c*16+e])^2)
// emb = feat[b,:,p].w[n,:], n=c*16+e, K=512.
// a = ah+al, b = bh+bl (exact fp16 splits).
// acc = ah*bh + ah*bl + al*bh issued per-fragment from ONE smem stage
// (single K pass; 1.5x less L2 traffic / ldsm / syncs than 3-pass version).
// CTA tile 256x128, warp tile 64x64 (8 warps), BK=32, 3-stage cp.async.
// ============================================================================

#define BM 256
#define BN 128
#define BK 32
#define KTILES 16            // 512 / 32
#define STAGE_BYTES 49152    // Ahi 16K | Alo 16K | Bhi 8K | Blo 8K
#define OFF_ALO 16384
#define OFF_BHI 32768
#define OFF_BLO 40960
#define CENT_OFF 147456
#define SMEM_TOTAL (147456 + 512)

// -------- device-global scratch (no cudaMalloc allowed) ----------------------
__device__ __half g_ah[67108864];   // [131072 px][512 k]
__device__ __half g_al[67108864];
__device__ __half g_bh[524288];     // [1024 n][512 k], n = c*16+e
__device__ __half g_bl[524288];
__device__ float  g_cent[1024];

// -------- helpers -------------------------------------------------------------
__device__ __forceinline__ uint32_t smem_u32(const void* p) {
    uint32_t a;
    asm("{ .reg .u64 t; cvta.to.shared.u64 t, %1; cvt.u32.u64 %0, t; }" : "=r"(a) : "l"(p));
    return a;
}
__device__ __forceinline__ void cp16(uint32_t dst, const __half* src) {
    asm volatile("cp.async.cg.shared.global [%0], [%1], 16;"
                 :: "r"(dst), "l"(__cvta_generic_to_global(src)));
}
__device__ __forceinline__ void ldsm4(uint32_t* r, uint32_t addr) {
    asm volatile("ldmatrix.sync.aligned.m8n8.x4.shared.b16 {%0,%1,%2,%3}, [%4];"
                 : "=r"(r[0]), "=r"(r[1]), "=r"(r[2]), "=r"(r[3]) : "r"(addr));
}
__device__ __forceinline__ void mma16816(float* c, const uint32_t* a, const uint32_t* b) {
    asm volatile("mma.sync.aligned.m16n8k16.row.col.f32.f16.f16.f32 "
                 "{%0,%1,%2,%3}, {%4,%5,%6,%7}, {%8,%9}, {%0,%1,%2,%3};"
                 : "+f"(c[0]), "+f"(c[1]), "+f"(c[2]), "+f"(c[3])
                 : "r"(a[0]), "r"(a[1]), "r"(a[2]), "r"(a[3]), "r"(b[0]), "r"(b[1]));
}

// -------- prep 1: transpose + fp16-split features ----------------------------
__global__ void prep_feat(const float* __restrict__ feat) {
    __shared__ float tile[32][33];
    int b = blockIdx.z;
    int p0 = blockIdx.x * 32, k0 = blockIdx.y * 32;
    int tx = threadIdx.x, ty = threadIdx.y;                // (32, 8)
    const float* src = feat + ((size_t)b * 512 + k0) * 16384 + p0;
#pragma unroll
    for (int i = 0; i < 4; i++)
        tile[ty + 8 * i][tx] = src[(size_t)(ty + 8 * i) * 16384 + tx];
    __syncthreads();
    size_t dbase = ((size_t)b * 16384 + p0) * 512 + k0;
#pragma unroll
    for (int i = 0; i < 4; i++) {
        int pr = ty + 8 * i;
        float v = tile[tx][pr];
        __half hi = __float2half_rn(v);
        __half lo = __float2half_rn(v - __half2float(hi));
        g_ah[dbase + (size_t)pr * 512 + tx] = hi;
        g_al[dbase + (size_t)pr * 512 + tx] = lo;
    }
}

// -------- prep 2: weights reorder + split, centroids --------------------------
__global__ void prep_w(const float* __restrict__ wgt, const float* __restrict__ m,
                       const float* __restrict__ Nb) {
    int n = blockIdx.x;                 // n = c*16 + e
    int c = n >> 4, e = n & 15;
    const float* src = wgt + ((size_t)e * 64 + c) * 512;
    for (int k = threadIdx.x; k < 512; k += 128) {
        float v = src[k];
        __half hi = __float2half_rn(v);
        g_bh[(size_t)n * 512 + k] = hi;
        g_bl[(size_t)n * 512 + k] = __float2half_rn(v - __half2float(hi));
    }
    if (threadIdx.x == 0) g_cent[n] = m[e * 64 + c] / Nb[c];
}

// -------- stage fill (256 threads): 12 x 16B cp.async per thread ---------------
// 64B rows (4 chunks), chunk swizzle: c ^ (row & 3)
__device__ __forceinline__ void fill_stage(uint32_t sb, int s, int kt, long P0, int n0, int t) {
    int kb = kt * BK;
    uint32_t st = sb + s * STAGE_BYTES;
    int r = t >> 2, c = t & 3;
    uint32_t sw = (uint32_t)((c ^ (r & 3)) << 4);
#pragma unroll
    for (int i = 0; i < 4; i++) {                 // Ahi / Alo: 256 rows x 4 chunks
        int rr = r + i * 64;
        uint32_t d = st + rr * 64 + (uint32_t)((c ^ (rr & 3)) << 4);
        cp16(d,           g_ah + (size_t)(P0 + rr) * 512 + kb + c * 8);
        cp16(d + OFF_ALO, g_al + (size_t)(P0 + rr) * 512 + kb + c * 8);
    }
#pragma unroll
    for (int i = 0; i < 2; i++) {                 // Bhi / Blo: 128 rows x 4 chunks
        int rr = r + i * 64;
        uint32_t d = st + OFF_BHI + rr * 64 + (uint32_t)((c ^ (rr & 3)) << 4);
        cp16(d,                     g_bh + (size_t)(n0 + rr) * 512 + kb + c * 8);
        cp16(d + (OFF_BLO - OFF_BHI), g_bl + (size_t)(n0 + rr) * 512 + kb + c * 8);
    }
    (void)sw;
}

// -------- main GEMM + fused RBF epilogue ---------------------------------------
__global__ __launch_bounds__(256, 1) void duq_mma(float* __restrict__ out) {
    extern __shared__ char smem[];
    uint32_t sb = smem_u32(smem);
    int t = threadIdx.x, l = t & 31, w = t >> 5;
    int nb = blockIdx.x, mb = blockIdx.y;
    long P0 = (long)mb * BM;           // 256 | 16384 -> never crosses a batch
    int n0 = nb * BN;

    if (t < 128) ((float*)(smem + CENT_OFF))[t] = g_cent[n0 + t];

    int wm = (w >> 1) * 64;            // 4 M-groups of 64
    int wn = (w & 1) * 64;             // 2 N-groups of 64

    int rl  = l & 7;                   // row within 8-row matrix
    int mh  = (l >> 3) & 1;            // matrix half bit
    int hi  = (l >> 4) & 1;            // k-chunk bit

    float acc[4][8][4];
#pragma unroll
    for (int i = 0; i < 4; i++)
#pragma unroll
        for (int j = 0; j < 8; j++)
#pragma unroll
            for (int q = 0; q < 4; q++) acc[i][j][q] = 0.0f;

    fill_stage(sb, 0, 0, P0, n0, t);
    asm volatile("cp.async.commit_group;" ::: "memory");
    fill_stage(sb, 1, 1, P0, n0, t);
    asm volatile("cp.async.commit_group;" ::: "memory");

    for (int kt = 0; kt < KTILES; kt++) {
        asm volatile("cp.async.wait_group 1;" ::: "memory");
        __syncthreads();

        if (kt + 2 < KTILES) fill_stage(sb, (kt + 2) % 3, kt + 2, P0, n0, t);
        asm volatile("cp.async.commit_group;" ::: "memory");

        uint32_t As = sb + (kt % 3) * STAGE_BYTES;
#pragma unroll
        for (int k16 = 0; k16 < 2; k16++) {
            // ---- A fragments, hi and lo ----
            uint32_t ah[4][4], al[4][4];
#pragma unroll
            for (int mf = 0; mf < 4; mf++) {
                int ra = wm + mf * 16 + mh * 8 + rl;
                uint32_t off = (uint32_t)(ra * 64 + (((2 * k16 + hi) ^ (rl & 3)) << 4));
                ldsm4(ah[mf], As + off);
                ldsm4(al[mf], As + OFF_ALO + off);
            }
            // ---- B fragments + 3-product MMAs per np group ----
#pragma unroll
            for (int np = 0; np < 4; np++) {
                int rb = wn + np * 16 + hi * 8 + rl;
                uint32_t off = (uint32_t)(rb * 64 + (((2 * k16 + mh) ^ (rl & 3)) << 4));
                uint32_t bh4[4], bl4[4];
                ldsm4(bh4, As + OFF_BHI + off);
                ldsm4(bl4, As + OFF_BLO + off);
#pragma unroll
                for (int mf = 0; mf < 4; mf++) {
                    mma16816(acc[mf][2 * np],     ah[mf], &bh4[0]);
                    mma16816(acc[mf][2 * np],     ah[mf], &bl4[0]);
                    mma16816(acc[mf][2 * np],     al[mf], &bh4[0]);
                    mma16816(acc[mf][2 * np + 1], ah[mf], &bh4[2]);
                    mma16816(acc[mf][2 * np + 1], ah[mf], &bl4[2]);
                    mma16816(acc[mf][2 * np + 1], al[mf], &bh4[2]);
                }
            }
        }
    }

    // ---- epilogue: diff^2, e-reduction (quad shuffles), expf, store ----
    const float* centS = (const float*)(smem + CENT_OFF);
    int q2 = l & 3;
    int cb = ((n0 + wn) >> 4);         // first of this warp's 4 channels

#pragma unroll
    for (int mf = 0; mf < 4; mf++) {
        float s[4][2];
#pragma unroll
        for (int ch = 0; ch < 4; ch++) { s[ch][0] = 0.0f; s[ch][1] = 0.0f; }
#pragma unroll
        for (int nf = 0; nf < 8; nf++) {
            int ch = nf >> 1;
#pragma unroll
            for (int j = 0; j < 2; j++) {
                float ce = centS[wn + nf * 8 + 2 * q2 + j];
                float d0 = acc[mf][nf][j]     - ce;
                float d1 = acc[mf][nf][2 + j] - ce;
                s[ch][0] = fmaf(d0, d0, s[ch][0]);
                s[ch][1] = fmaf(d1, d1, s[ch][1]);
            }
        }
#pragma unroll
        for (int ch = 0; ch < 4; ch++)
#pragma unroll
            for (int r = 0; r < 2; r++) {
                s[ch][r] += __shfl_xor_sync(0xFFFFFFFFu, s[ch][r], 1);
                s[ch][r] += __shfl_xor_sync(0xFFFFFFFFu, s[ch][r], 2);
            }
        float v0 = (q2 == 0) ? s[0][0] : (q2 == 1) ? s[1][0] : (q2 == 2) ? s[2][0] : s[3][0];
        float v1 = (q2 == 0) ? s[0][1] : (q2 == 1) ? s[1][1] : (q2 == 2) ? s[2][1] : s[3][1];

        long gp = P0 + wm + mf * 16 + (l >> 2);
        int b   = (int)(gp >> 14);
        int pin = (int)(gp & 16383);
        int ch  = cb + q2;
        float* o = out + ((size_t)b * 64 + ch) * 16384 + pin;
        o[0] = expf(-3.125f * v0);
        o[8] = expf(-3.125f * v1);
    }
}

// -------- launch ----------------------------------------------------------------
extern "C" void kernel_launch(void* const* d_in, const int* in_sizes, int n_in,
                              void* d_out, int out_size)
{
    const float* feat = (const float*)d_in[0];   // [8, 512, 128, 128]
    const float* wgt  = (const float*)d_in[1];   // [16, 64, 512]
    const float* m    = (const float*)d_in[2];   // [16, 64]
    const float* N    = (const float*)d_in[3];   // [64]
    float* out        = (float*)d_out;           // [8, 64, 128, 128]

    cudaFuncSetAttribute(duq_mma, cudaFuncAttributeMaxDynamicSharedMemorySize, SMEM_TOTAL);

    prep_feat<<<dim3(512, 16, 8), dim3(32, 8)>>>(feat);
    prep_w<<<1024, 128>>>(wgt, m, N);
    duq_mma<<<dim3(8, 512), 256, SMEM_TOTAL>>>(out);
}